// round 1
// baseline (speedup 1.0000x reference)
#include <cuda_runtime.h>
#include <math.h>

#define NN 100000
#define EE 300000
#define DD 256
#define FDIM 512
#define LL 5
#define GG 4000
#define NUM_BOND_C 2
#define BN_EPS 1e-5f

// ---------------- scratch (device globals: no allocation allowed) ----------------
__device__ float g_h[(size_t)NN * DD];       // node features       [N,256]
__device__ float g_agg[(size_t)NN * DD];     // aggregated messages [N,256]
__device__ float g_tmp[(size_t)NN * FDIM];   // MLP hidden / feat   [N,512]
__device__ float g_stat[2 * DD];             // BN sum / sumsq
__device__ float g_ab[2 * DD];               // BN folded scale / shift
__device__ float g_ssum[(size_t)GG * FDIM];  // pooled sums
__device__ float g_cnt[GG];                  // per-graph node counts
__device__ float g_gfeat[(size_t)GG * FDIM]; // pooled means
__device__ float g_hid[(size_t)GG * (FDIM / 2)];

__device__ __forceinline__ float softplus_f(float x) {
    return fmaxf(x, 0.0f) + log1pf(expf(-fabsf(x)));
}

// ---------------- init: h = x_emb1[atomics] + pos @ x_emb2_w + b ----------------
__global__ void init_h_kernel(const int* __restrict__ atomics,
                              const float* __restrict__ pos,
                              const float* __restrict__ emb1,
                              const float* __restrict__ w2,
                              const float* __restrict__ b2,
                              float* __restrict__ h) {
    size_t idx = (size_t)blockIdx.x * blockDim.x + threadIdx.x;
    if (idx >= (size_t)NN * DD) return;
    int i = (int)(idx / DD);
    int d = (int)(idx & (DD - 1));
    float p0 = pos[i * 3 + 0], p1 = pos[i * 3 + 1], p2 = pos[i * 3 + 2];
    float v = emb1[(size_t)atomics[i] * DD + d];
    v += p0 * w2[d] + p1 * w2[DD + d] + p2 * w2[2 * DD + d] + b2[d];
    h[idx] = v;
}

// ---------------- agg = h + edge_emb[l][self_loop_bond] ----------------
__global__ void agg_init_kernel(const float* __restrict__ h,
                                const float* __restrict__ emb_self, // [256]
                                float* __restrict__ agg) {
    size_t idx = (size_t)blockIdx.x * blockDim.x + threadIdx.x;
    if (idx >= (size_t)NN * DD) return;
    int d = (int)(idx & (DD - 1));
    agg[idx] = h[idx] + emb_self[d];
}

// ---------------- scatter-add edges: agg[dst] += h[src] + emb[eattr] ----------------
__global__ void scatter_edges_kernel(const float* __restrict__ h,
                                     const int* __restrict__ edge_index, // [2,E]
                                     const int* __restrict__ edge_attr,  // [E]
                                     const float* __restrict__ emb,      // [NUM_BOND,256] layer slice
                                     float* __restrict__ agg) {
    int e = blockIdx.x * (blockDim.x >> 5) + (threadIdx.x >> 5);
    if (e >= EE) return;
    int lane = threadIdx.x & 31;
    int s = edge_index[e];
    int t = edge_index[EE + e];
    const float* hs = h + (size_t)s * DD;
    const float* eb = emb + (size_t)edge_attr[e] * DD;
    float* ag = agg + (size_t)t * DD;
#pragma unroll
    for (int half = 0; half < 2; half++) {
        int c = lane * 4 + half * 128;
        float4 hv = *(const float4*)(hs + c);
        float4 ev = *(const float4*)(eb + c);
        atomicAdd(ag + c + 0, hv.x + ev.x);
        atomicAdd(ag + c + 1, hv.y + ev.y);
        atomicAdd(ag + c + 2, hv.z + ev.z);
        atomicAdd(ag + c + 3, hv.w + ev.w);
    }
}

// ---------------- GEMM: C[M,Nc] = act(A[M,K] @ B[K,Nc] + bias) ----------------
// 128x128 tile, BK=8, 256 threads, 8x8 micro-tile per thread.
__global__ __launch_bounds__(256, 2)
void gemm_bias_act(const float* __restrict__ A, const float* __restrict__ B,
                   const float* __restrict__ bias, float* __restrict__ C,
                   int M, int K, int Nc, int act) {
    __shared__ float As[8][132];  // padded: conflict-free transposed stores / fl4 loads
    __shared__ float Bs[8][128];

    const int tid = threadIdx.x;
    const int tx = tid & 15;
    const int ty = tid >> 4;
    const int brow = blockIdx.y * 128;
    const int bcol = blockIdx.x * 128;

    const int a_row = tid >> 1;          // 0..127
    const int a_k4 = (tid & 1) * 4;      // 0 or 4
    const int b_k = tid >> 5;            // 0..7
    const int b_c4 = (tid & 31) * 4;     // 0..124

    float acc[8][8];
#pragma unroll
    for (int i = 0; i < 8; i++)
#pragma unroll
        for (int j = 0; j < 8; j++) acc[i][j] = 0.0f;

    for (int k0 = 0; k0 < K; k0 += 8) {
        float4 av = make_float4(0.f, 0.f, 0.f, 0.f);
        int gr = brow + a_row;
        if (gr < M) av = *(const float4*)(A + (size_t)gr * K + k0 + a_k4);
        As[a_k4 + 0][a_row] = av.x;
        As[a_k4 + 1][a_row] = av.y;
        As[a_k4 + 2][a_row] = av.z;
        As[a_k4 + 3][a_row] = av.w;
        float4 bv = *(const float4*)(B + (size_t)(k0 + b_k) * Nc + bcol + b_c4);
        *(float4*)&Bs[b_k][b_c4] = bv;
        __syncthreads();
#pragma unroll
        for (int k = 0; k < 8; k++) {
            float4 a0 = *(const float4*)&As[k][ty * 4];
            float4 a1 = *(const float4*)&As[k][64 + ty * 4];
            float4 b0 = *(const float4*)&Bs[k][tx * 4];
            float4 b1 = *(const float4*)&Bs[k][64 + tx * 4];
            float ar[8] = {a0.x, a0.y, a0.z, a0.w, a1.x, a1.y, a1.z, a1.w};
            float br[8] = {b0.x, b0.y, b0.z, b0.w, b1.x, b1.y, b1.z, b1.w};
#pragma unroll
            for (int i = 0; i < 8; i++)
#pragma unroll
                for (int j = 0; j < 8; j++) acc[i][j] = fmaf(ar[i], br[j], acc[i][j]);
        }
        __syncthreads();
    }

#pragma unroll
    for (int i = 0; i < 8; i++) {
        int row = brow + ((i < 4) ? (ty * 4 + i) : (64 + ty * 4 + i - 4));
        if (row >= M) continue;
#pragma unroll
        for (int j = 0; j < 8; j++) {
            int col = bcol + ((j < 4) ? (tx * 4 + j) : (64 + tx * 4 + j - 4));
            float v = acc[i][j] + bias[col];
            if (act) v = softplus_f(v);
            C[(size_t)row * Nc + col] = v;
        }
    }
}

// ---------------- BN ----------------
__global__ void zero_kernel(float* __restrict__ p, size_t n) {
    size_t idx = (size_t)blockIdx.x * blockDim.x + threadIdx.x;
    if (idx < n) p[idx] = 0.0f;
}

__global__ void bn_stats_kernel(const float* __restrict__ h, float* __restrict__ stat) {
    int d = threadIdx.x;  // 256 threads, one channel each
    float s = 0.f, ss = 0.f;
    for (int r = blockIdx.x; r < NN; r += gridDim.x) {
        float v = h[(size_t)r * DD + d];
        s += v;
        ss += v * v;
    }
    atomicAdd(&stat[d], s);
    atomicAdd(&stat[DD + d], ss);
}

__global__ void bn_finalize_kernel(const float* __restrict__ stat,
                                   const float* __restrict__ gamma,
                                   const float* __restrict__ beta,
                                   float* __restrict__ ab) {
    int d = threadIdx.x;
    float mean = stat[d] * (1.0f / NN);
    float var = stat[DD + d] * (1.0f / NN) - mean * mean;
    float inv = rsqrtf(var + BN_EPS);
    float a = gamma[d] * inv;
    ab[d] = a;
    ab[DD + d] = beta[d] - mean * a;
}

__global__ void bn_apply_kernel(float* __restrict__ h, const float* __restrict__ ab, int act) {
    size_t idx = (size_t)blockIdx.x * blockDim.x + threadIdx.x;
    if (idx >= (size_t)NN * DD) return;
    int d = (int)(idx & (DD - 1));
    float v = h[idx] * ab[d] + ab[DD + d];
    if (act) v = softplus_f(v);
    h[idx] = v;
}

// ---------------- pooling ----------------
__global__ void pool_count_kernel(const int* __restrict__ batch, float* __restrict__ cnt) {
    int i = blockIdx.x * blockDim.x + threadIdx.x;
    if (i >= NN) return;
    atomicAdd(&cnt[batch[i]], 1.0f);
}

// batch is sorted: each thread handles 8 consecutive nodes for one channel,
// accumulating per-graph runs locally before atomics (~8x fewer atomics).
__global__ void pool_sum_kernel(const float* __restrict__ feat,
                                const int* __restrict__ batch,
                                float* __restrict__ ssum) {
    size_t idx = (size_t)blockIdx.x * blockDim.x + threadIdx.x;
    const size_t nchunks = (NN + 7) / 8;
    if (idx >= nchunks * FDIM) return;
    int f = (int)(idx & (FDIM - 1));
    int i0 = (int)(idx / FDIM) * 8;
    int cur = batch[i0];
    float acc = 0.f;
#pragma unroll
    for (int r = 0; r < 8; r++) {
        int i = i0 + r;
        if (i >= NN) break;
        int b = batch[i];
        if (b != cur) {
            atomicAdd(&ssum[(size_t)cur * FDIM + f], acc);
            acc = 0.f;
            cur = b;
        }
        acc += feat[(size_t)i * FDIM + f];
    }
    atomicAdd(&ssum[(size_t)cur * FDIM + f], acc);
}

__global__ void gfeat_kernel(const float* __restrict__ ssum, const float* __restrict__ cnt,
                             float* __restrict__ gfeat) {
    size_t idx = (size_t)blockIdx.x * blockDim.x + threadIdx.x;
    if (idx >= (size_t)GG * FDIM) return;
    int g = (int)(idx / FDIM);
    gfeat[idx] = ssum[idx] / fmaxf(cnt[g], 1.0f);
}

// ---------------- final head: out[g] = dot(hid[g], w2) + b2 ----------------
__global__ void head_out_kernel(const float* __restrict__ hid, const float* __restrict__ w2,
                                const float* __restrict__ b2, float* __restrict__ out) {
    int g = blockIdx.x * (blockDim.x >> 5) + (threadIdx.x >> 5);
    if (g >= GG) return;
    int lane = threadIdx.x & 31;
    const float* hr = hid + (size_t)g * (FDIM / 2);
    float s = 0.f;
#pragma unroll
    for (int k = lane; k < FDIM / 2; k += 32) s += hr[k] * w2[k];
#pragma unroll
    for (int o = 16; o; o >>= 1) s += __shfl_down_sync(0xffffffffu, s, o);
    if (lane == 0) out[g] = s + b2[0];
}

// ---------------- host launch ----------------
static inline void launch_gemm(const float* A, const float* B, const float* bias, float* C,
                               int M, int K, int Nc, int act) {
    dim3 grid((Nc + 127) / 128, (M + 127) / 128);
    gemm_bias_act<<<grid, 256>>>(A, B, bias, C, M, K, Nc, act);
}

extern "C" void kernel_launch(void* const* d_in, const int* in_sizes, int n_in,
                              void* d_out, int out_size) {
    const int* atomics = (const int*)d_in[0];
    const float* pos = (const float*)d_in[1];
    const int* edge_index = (const int*)d_in[2];
    const int* edge_attr = (const int*)d_in[3];
    const int* batch = (const int*)d_in[4];
    const float* x_emb1 = (const float*)d_in[5];
    const float* x_emb2_w = (const float*)d_in[6];
    const float* x_emb2_b = (const float*)d_in[7];
    const float* edge_emb = (const float*)d_in[8];
    const float* mlp_w1 = (const float*)d_in[9];
    const float* mlp_b1 = (const float*)d_in[10];
    const float* mlp_w2 = (const float*)d_in[11];
    const float* mlp_b2 = (const float*)d_in[12];
    const float* bn_gamma = (const float*)d_in[13];
    const float* bn_beta = (const float*)d_in[14];
    const float* feat_w = (const float*)d_in[15];
    const float* feat_b = (const float*)d_in[16];
    const float* head_w1 = (const float*)d_in[17];
    const float* head_b1 = (const float*)d_in[18];
    const float* head_w2 = (const float*)d_in[19];
    const float* head_b2 = (const float*)d_in[20];
    float* out = (float*)d_out;

    float *h, *agg, *tmp, *stat, *ab, *ssum, *cnt, *gfeat, *hid;
    cudaGetSymbolAddress((void**)&h, g_h);
    cudaGetSymbolAddress((void**)&agg, g_agg);
    cudaGetSymbolAddress((void**)&tmp, g_tmp);
    cudaGetSymbolAddress((void**)&stat, g_stat);
    cudaGetSymbolAddress((void**)&ab, g_ab);
    cudaGetSymbolAddress((void**)&ssum, g_ssum);
    cudaGetSymbolAddress((void**)&cnt, g_cnt);
    cudaGetSymbolAddress((void**)&gfeat, g_gfeat);
    cudaGetSymbolAddress((void**)&hid, g_hid);

    const size_t ND = (size_t)NN * DD;
    const int EL = 256;

    // initial node features
    init_h_kernel<<<(unsigned)((ND + EL - 1) / EL), EL>>>(atomics, pos, x_emb1, x_emb2_w,
                                                          x_emb2_b, h);

    for (int l = 0; l < LL; l++) {
        const float* emb_l = edge_emb + (size_t)l * NUM_BOND_C * DD;
        const float* emb_self = emb_l + (size_t)(NUM_BOND_C - 1) * DD;

        // agg = h + self-loop message, then scatter real edges
        agg_init_kernel<<<(unsigned)((ND + EL - 1) / EL), EL>>>(h, emb_self, agg);
        scatter_edges_kernel<<<(EE + 7) / 8, 256>>>(h, edge_index, edge_attr, emb_l, agg);

        // MLP: softplus(agg@W1+b1)@W2+b2  -> h
        launch_gemm(agg, mlp_w1 + (size_t)l * DD * 2 * DD, mlp_b1 + (size_t)l * 2 * DD,
                    tmp, NN, DD, 2 * DD, 1);
        launch_gemm(tmp, mlp_w2 + (size_t)l * 2 * DD * DD, mlp_b2 + (size_t)l * DD,
                    h, NN, 2 * DD, DD, 0);

        // BatchNorm (+ softplus except last layer)
        zero_kernel<<<2, 256>>>(stat, 2 * DD);
        bn_stats_kernel<<<512, 256>>>(h, stat);
        bn_finalize_kernel<<<1, 256>>>(stat, bn_gamma + (size_t)l * DD,
                                       bn_beta + (size_t)l * DD, ab);
        bn_apply_kernel<<<(unsigned)((ND + EL - 1) / EL), EL>>>(h, ab, (l < LL - 1) ? 1 : 0);
    }

    // feat = h @ feat_w + feat_b   (reuse tmp as [N,512] feat buffer)
    launch_gemm(h, feat_w, feat_b, tmp, NN, DD, FDIM, 0);

    // global mean pool
    zero_kernel<<<(unsigned)(((size_t)GG * FDIM + EL - 1) / EL), EL>>>(ssum, (size_t)GG * FDIM);
    zero_kernel<<<(GG + EL - 1) / EL, EL>>>(cnt, GG);
    pool_count_kernel<<<(NN + EL - 1) / EL, EL>>>(batch, cnt);
    {
        size_t total = ((NN + 7) / 8) * (size_t)FDIM;
        pool_sum_kernel<<<(unsigned)((total + EL - 1) / EL), EL>>>(tmp, batch, ssum);
    }
    gfeat_kernel<<<(unsigned)(((size_t)GG * FDIM + EL - 1) / EL), EL>>>(ssum, cnt, gfeat);

    // head
    launch_gemm(gfeat, head_w1, head_b1, hid, GG, FDIM, FDIM / 2, 1);
    head_out_kernel<<<(GG + 7) / 8, 256>>>(hid, head_w2, head_b2, out);
}

// round 2
// speedup vs baseline: 1.2819x; 1.2819x over previous
#include <cuda_runtime.h>
#include <math.h>

#define NN 100000
#define EE 300000
#define DD 256
#define FDIM 512
#define LL 5
#define GG 4000
#define NUM_BOND_C 2
#define BN_EPS 1e-5f

// ---------------- scratch (device globals: no allocation allowed) ----------------
__device__ float g_h[(size_t)NN * DD];
__device__ float g_agg[(size_t)NN * DD];
__device__ float g_tmp[(size_t)NN * FDIM];
__device__ float g_stat[2 * DD];
__device__ float g_ab[2 * DD];
__device__ float g_ssum[(size_t)GG * FDIM];
__device__ float g_cnt[GG];
__device__ float g_gfeat[(size_t)GG * FDIM];
__device__ float g_hid[(size_t)GG * (FDIM / 2)];

__device__ __forceinline__ float softplus_f(float x) {
    return fmaxf(x, 0.0f) + log1pf(expf(-fabsf(x)));
}

__device__ __forceinline__ void red_add_v4(float* p, float x, float y, float z, float w) {
    asm volatile("red.global.add.v4.f32 [%0], {%1,%2,%3,%4};"
                 :: "l"(p), "f"(x), "f"(y), "f"(z), "f"(w) : "memory");
}

// ---------------- init: h = x_emb1[atomics] + pos @ x_emb2_w + b ----------------
__global__ void init_h_kernel(const int* __restrict__ atomics,
                              const float* __restrict__ pos,
                              const float* __restrict__ emb1,
                              const float* __restrict__ w2,
                              const float* __restrict__ b2,
                              float* __restrict__ h) {
    size_t idx = (size_t)blockIdx.x * blockDim.x + threadIdx.x;
    if (idx >= (size_t)NN * DD) return;
    int i = (int)(idx / DD);
    int d = (int)(idx & (DD - 1));
    float p0 = pos[i * 3 + 0], p1 = pos[i * 3 + 1], p2 = pos[i * 3 + 2];
    float v = emb1[(size_t)atomics[i] * DD + d];
    v += p0 * w2[d] + p1 * w2[DD + d] + p2 * w2[2 * DD + d] + b2[d];
    h[idx] = v;
}

// ---------------- agg = h + emb_self (float4) ----------------
__global__ void agg_init_kernel(const float* __restrict__ h,
                                const float* __restrict__ emb_self,
                                float* __restrict__ agg) {
    size_t idx = (size_t)blockIdx.x * blockDim.x + threadIdx.x;
    if (idx >= (size_t)NN * DD / 4) return;
    int d4 = (int)(idx & (DD / 4 - 1)) * 4;
    float4 hv = *((const float4*)h + idx);
    float4 ev = *(const float4*)(emb_self + d4);
    float4 o = make_float4(hv.x + ev.x, hv.y + ev.y, hv.z + ev.z, hv.w + ev.w);
    *((float4*)agg + idx) = o;
}

// ---------------- scatter-add edges: agg[dst] += h[src] + emb[eattr] ----------------
__global__ void scatter_edges_kernel(const float* __restrict__ h,
                                     const int* __restrict__ edge_index,
                                     const int* __restrict__ edge_attr,
                                     const float* __restrict__ emb,
                                     float* __restrict__ agg) {
    int e = blockIdx.x * (blockDim.x >> 5) + (threadIdx.x >> 5);
    if (e >= EE) return;
    int lane = threadIdx.x & 31;
    int s = edge_index[e];
    int t = edge_index[EE + e];
    const float* hs = h + (size_t)s * DD;
    const float* eb = emb + (size_t)edge_attr[e] * DD;
    float* ag = agg + (size_t)t * DD;
#pragma unroll
    for (int half = 0; half < 2; half++) {
        int c = lane * 4 + half * 128;
        float4 hv = *(const float4*)(hs + c);
        float4 ev = *(const float4*)(eb + c);
        red_add_v4(ag + c, hv.x + ev.x, hv.y + ev.y, hv.z + ev.z, hv.w + ev.w);
    }
}

// ---------------- GEMM: C = act(A @ B + bias), optional BN-stats epilogue ----------
// 128x128 tile, BK=16, 256 threads, 8x8 micro-tile, double-buffered smem,
// one __syncthreads per K-tile.
__global__ __launch_bounds__(256, 2)
void gemm_dbuf(const float* __restrict__ A, const float* __restrict__ B,
               const float* __restrict__ bias, float* __restrict__ C,
               int M, int K, int Nc, int act, float* __restrict__ stat) {
    __shared__ float As[2][16][132];
    __shared__ float Bs[2][16][128];
    __shared__ float s_sum[128];
    __shared__ float s_sq[128];

    const int tid = threadIdx.x;
    const int tx = tid & 15;
    const int ty = tid >> 4;
    const int brow = blockIdx.y * 128;
    const int bcol = blockIdx.x * 128;

    const int a_row = tid >> 1;
    const int a_k = (tid & 1) * 4;
    const int b_k = tid >> 5;
    const int b_c = (tid & 31) * 4;

    const float* Aptr = A + (size_t)(brow + a_row) * K + a_k;
    const bool a_ok = (brow + a_row) < M;
    const float* Bptr = B + (size_t)b_k * Nc + bcol + b_c;

    const float4 fz = make_float4(0.f, 0.f, 0.f, 0.f);
    float4 pa0 = a_ok ? *(const float4*)Aptr : fz;
    float4 pa1 = a_ok ? *(const float4*)(Aptr + 8) : fz;
    float4 pb0 = *(const float4*)Bptr;
    float4 pb1 = *(const float4*)(Bptr + (size_t)8 * Nc);

    float acc[8][8];
#pragma unroll
    for (int i = 0; i < 8; i++)
#pragma unroll
        for (int j = 0; j < 8; j++) acc[i][j] = 0.0f;

    int buf = 0;
    As[0][a_k + 0][a_row] = pa0.x;
    As[0][a_k + 1][a_row] = pa0.y;
    As[0][a_k + 2][a_row] = pa0.z;
    As[0][a_k + 3][a_row] = pa0.w;
    As[0][a_k + 8][a_row] = pa1.x;
    As[0][a_k + 9][a_row] = pa1.y;
    As[0][a_k + 10][a_row] = pa1.z;
    As[0][a_k + 11][a_row] = pa1.w;
    *(float4*)&Bs[0][b_k][b_c] = pb0;
    *(float4*)&Bs[0][b_k + 8][b_c] = pb1;
    __syncthreads();

    for (int k0 = 16; k0 < K; k0 += 16) {
        pa0 = a_ok ? *(const float4*)(Aptr + k0) : fz;
        pa1 = a_ok ? *(const float4*)(Aptr + k0 + 8) : fz;
        pb0 = *(const float4*)(Bptr + (size_t)k0 * Nc);
        pb1 = *(const float4*)(Bptr + (size_t)(k0 + 8) * Nc);

#pragma unroll
        for (int k = 0; k < 16; k++) {
            float4 a0 = *(const float4*)&As[buf][k][ty * 4];
            float4 a1 = *(const float4*)&As[buf][k][64 + ty * 4];
            float4 b0 = *(const float4*)&Bs[buf][k][tx * 4];
            float4 b1 = *(const float4*)&Bs[buf][k][64 + tx * 4];
            float ar[8] = {a0.x, a0.y, a0.z, a0.w, a1.x, a1.y, a1.z, a1.w};
            float br[8] = {b0.x, b0.y, b0.z, b0.w, b1.x, b1.y, b1.z, b1.w};
#pragma unroll
            for (int i = 0; i < 8; i++)
#pragma unroll
                for (int j = 0; j < 8; j++) acc[i][j] = fmaf(ar[i], br[j], acc[i][j]);
        }
        buf ^= 1;
        As[buf][a_k + 0][a_row] = pa0.x;
        As[buf][a_k + 1][a_row] = pa0.y;
        As[buf][a_k + 2][a_row] = pa0.z;
        As[buf][a_k + 3][a_row] = pa0.w;
        As[buf][a_k + 8][a_row] = pa1.x;
        As[buf][a_k + 9][a_row] = pa1.y;
        As[buf][a_k + 10][a_row] = pa1.z;
        As[buf][a_k + 11][a_row] = pa1.w;
        *(float4*)&Bs[buf][b_k][b_c] = pb0;
        *(float4*)&Bs[buf][b_k + 8][b_c] = pb1;
        __syncthreads();
    }

#pragma unroll
    for (int k = 0; k < 16; k++) {
        float4 a0 = *(const float4*)&As[buf][k][ty * 4];
        float4 a1 = *(const float4*)&As[buf][k][64 + ty * 4];
        float4 b0 = *(const float4*)&Bs[buf][k][tx * 4];
        float4 b1 = *(const float4*)&Bs[buf][k][64 + tx * 4];
        float ar[8] = {a0.x, a0.y, a0.z, a0.w, a1.x, a1.y, a1.z, a1.w};
        float br[8] = {b0.x, b0.y, b0.z, b0.w, b1.x, b1.y, b1.z, b1.w};
#pragma unroll
        for (int i = 0; i < 8; i++)
#pragma unroll
            for (int j = 0; j < 8; j++) acc[i][j] = fmaf(ar[i], br[j], acc[i][j]);
    }

    // ---------------- epilogue ----------------
    const bool do_stats = (stat != nullptr);
    if (do_stats) {
        __syncthreads();
        if (tid < 128) { s_sum[tid] = 0.f; s_sq[tid] = 0.f; }
        __syncthreads();
    }

    float bl[8];
#pragma unroll
    for (int j = 0; j < 8; j++) {
        int coll = (j < 4) ? (tx * 4 + j) : (64 + tx * 4 + j - 4);
        bl[j] = bias[bcol + coll];
    }

    float csum[8], csq[8];
#pragma unroll
    for (int j = 0; j < 8; j++) { csum[j] = 0.f; csq[j] = 0.f; }

#pragma unroll
    for (int i = 0; i < 8; i++) {
        int row = brow + ((i < 4) ? (ty * 4 + i) : (64 + ty * 4 + i - 4));
        if (row >= M) continue;
        float v[8];
#pragma unroll
        for (int j = 0; j < 8; j++) {
            float x = acc[i][j] + bl[j];
            if (act) x = softplus_f(x);
            v[j] = x;
            csum[j] += x;
            csq[j] += x * x;
        }
        float* crow = C + (size_t)row * Nc + bcol;
        *(float4*)(crow + tx * 4) = make_float4(v[0], v[1], v[2], v[3]);
        *(float4*)(crow + 64 + tx * 4) = make_float4(v[4], v[5], v[6], v[7]);
    }

    if (do_stats) {
#pragma unroll
        for (int j = 0; j < 8; j++) {
            int coll = (j < 4) ? (tx * 4 + j) : (64 + tx * 4 + j - 4);
            atomicAdd(&s_sum[coll], csum[j]);
            atomicAdd(&s_sq[coll], csq[j]);
        }
        __syncthreads();
        if (tid < 128) {
            atomicAdd(&stat[bcol + tid], s_sum[tid]);
            atomicAdd(&stat[Nc + bcol + tid], s_sq[tid]);
        }
    }
}

// ---------------- BN ----------------
__global__ void zero_kernel(float* __restrict__ p, size_t n) {
    size_t idx = (size_t)blockIdx.x * blockDim.x + threadIdx.x;
    if (idx < n) p[idx] = 0.0f;
}

__global__ void bn_finalize_kernel(const float* __restrict__ stat,
                                   const float* __restrict__ gamma,
                                   const float* __restrict__ beta,
                                   float* __restrict__ ab) {
    int d = threadIdx.x;
    float mean = stat[d] * (1.0f / NN);
    float var = stat[DD + d] * (1.0f / NN) - mean * mean;
    float inv = rsqrtf(var + BN_EPS);
    float a = gamma[d] * inv;
    ab[d] = a;
    ab[DD + d] = beta[d] - mean * a;
}

// h = [softplus](h*a + b);  optional agg = h + emb_next (next layer's self-loop msg)
__global__ void bn_apply_agg_kernel(float* __restrict__ h, const float* __restrict__ ab,
                                    const float* __restrict__ emb_next,
                                    float* __restrict__ agg, int act) {
    size_t idx = (size_t)blockIdx.x * blockDim.x + threadIdx.x;
    if (idx >= (size_t)NN * DD / 4) return;
    int d4 = (int)(idx & (DD / 4 - 1)) * 4;
    float4 v = *((float4*)h + idx);
    float4 a = *(const float4*)(ab + d4);
    float4 b = *(const float4*)(ab + DD + d4);
    v.x = v.x * a.x + b.x;
    v.y = v.y * a.y + b.y;
    v.z = v.z * a.z + b.z;
    v.w = v.w * a.w + b.w;
    if (act) {
        v.x = softplus_f(v.x);
        v.y = softplus_f(v.y);
        v.z = softplus_f(v.z);
        v.w = softplus_f(v.w);
    }
    *((float4*)h + idx) = v;
    if (agg) {
        float4 e = *(const float4*)(emb_next + d4);
        *((float4*)agg + idx) = make_float4(v.x + e.x, v.y + e.y, v.z + e.z, v.w + e.w);
    }
}

// ---------------- pooling ----------------
__global__ void pool_count_kernel(const int* __restrict__ batch, float* __restrict__ cnt) {
    int i = blockIdx.x * blockDim.x + threadIdx.x;
    if (i >= NN) return;
    atomicAdd(&cnt[batch[i]], 1.0f);
}

// sorted batch: thread handles 4 channels x 8 consecutive nodes; per-run local acc.
__global__ void pool_sum_kernel(const float* __restrict__ feat,
                                const int* __restrict__ batch,
                                float* __restrict__ ssum) {
    size_t idx = (size_t)blockIdx.x * blockDim.x + threadIdx.x;
    const int CH = FDIM / 4;
    const size_t nchunks = (NN + 7) / 8;
    if (idx >= nchunks * CH) return;
    int f4 = (int)(idx & (CH - 1)) * 4;
    int i0 = (int)(idx / CH) * 8;
    int cur = batch[i0];
    float4 acc = make_float4(0.f, 0.f, 0.f, 0.f);
#pragma unroll
    for (int r = 0; r < 8; r++) {
        int i = i0 + r;
        if (i >= NN) break;
        int b = batch[i];
        if (b != cur) {
            red_add_v4(&ssum[(size_t)cur * FDIM + f4], acc.x, acc.y, acc.z, acc.w);
            acc = make_float4(0.f, 0.f, 0.f, 0.f);
            cur = b;
        }
        float4 v = *(const float4*)(feat + (size_t)i * FDIM + f4);
        acc.x += v.x; acc.y += v.y; acc.z += v.z; acc.w += v.w;
    }
    red_add_v4(&ssum[(size_t)cur * FDIM + f4], acc.x, acc.y, acc.z, acc.w);
}

__global__ void gfeat_kernel(const float* __restrict__ ssum, const float* __restrict__ cnt,
                             float* __restrict__ gfeat) {
    size_t idx = (size_t)blockIdx.x * blockDim.x + threadIdx.x;
    if (idx >= (size_t)GG * FDIM) return;
    int g = (int)(idx / FDIM);
    gfeat[idx] = ssum[idx] / fmaxf(cnt[g], 1.0f);
}

// ---------------- final head ----------------
__global__ void head_out_kernel(const float* __restrict__ hid, const float* __restrict__ w2,
                                const float* __restrict__ b2, float* __restrict__ out) {
    int g = blockIdx.x * (blockDim.x >> 5) + (threadIdx.x >> 5);
    if (g >= GG) return;
    int lane = threadIdx.x & 31;
    const float* hr = hid + (size_t)g * (FDIM / 2);
    float s = 0.f;
#pragma unroll
    for (int k = lane; k < FDIM / 2; k += 32) s += hr[k] * w2[k];
#pragma unroll
    for (int o = 16; o; o >>= 1) s += __shfl_down_sync(0xffffffffu, s, o);
    if (lane == 0) out[g] = s + b2[0];
}

// ---------------- host launch ----------------
static inline void launch_gemm(const float* A, const float* B, const float* bias, float* C,
                               int M, int K, int Nc, int act, float* stat) {
    dim3 grid((Nc + 127) / 128, (M + 127) / 128);
    gemm_dbuf<<<grid, 256>>>(A, B, bias, C, M, K, Nc, act, stat);
}

extern "C" void kernel_launch(void* const* d_in, const int* in_sizes, int n_in,
                              void* d_out, int out_size) {
    const int* atomics = (const int*)d_in[0];
    const float* pos = (const float*)d_in[1];
    const int* edge_index = (const int*)d_in[2];
    const int* edge_attr = (const int*)d_in[3];
    const int* batch = (const int*)d_in[4];
    const float* x_emb1 = (const float*)d_in[5];
    const float* x_emb2_w = (const float*)d_in[6];
    const float* x_emb2_b = (const float*)d_in[7];
    const float* edge_emb = (const float*)d_in[8];
    const float* mlp_w1 = (const float*)d_in[9];
    const float* mlp_b1 = (const float*)d_in[10];
    const float* mlp_w2 = (const float*)d_in[11];
    const float* mlp_b2 = (const float*)d_in[12];
    const float* bn_gamma = (const float*)d_in[13];
    const float* bn_beta = (const float*)d_in[14];
    const float* feat_w = (const float*)d_in[15];
    const float* feat_b = (const float*)d_in[16];
    const float* head_w1 = (const float*)d_in[17];
    const float* head_b1 = (const float*)d_in[18];
    const float* head_w2 = (const float*)d_in[19];
    const float* head_b2 = (const float*)d_in[20];
    float* out = (float*)d_out;

    float *h, *agg, *tmp, *stat, *ab, *ssum, *cnt, *gfeat, *hid;
    cudaGetSymbolAddress((void**)&h, g_h);
    cudaGetSymbolAddress((void**)&agg, g_agg);
    cudaGetSymbolAddress((void**)&tmp, g_tmp);
    cudaGetSymbolAddress((void**)&stat, g_stat);
    cudaGetSymbolAddress((void**)&ab, g_ab);
    cudaGetSymbolAddress((void**)&ssum, g_ssum);
    cudaGetSymbolAddress((void**)&cnt, g_cnt);
    cudaGetSymbolAddress((void**)&gfeat, g_gfeat);
    cudaGetSymbolAddress((void**)&hid, g_hid);

    const size_t ND = (size_t)NN * DD;
    const size_t ND4 = ND / 4;
    const int EL = 256;

    init_h_kernel<<<(unsigned)((ND + EL - 1) / EL), EL>>>(atomics, pos, x_emb1, x_emb2_w,
                                                          x_emb2_b, h);

    // layer 0 agg init (self-loop message uses bond type NUM_BOND-1)
    {
        const float* emb_self0 =
            edge_emb + (size_t)0 * NUM_BOND_C * DD + (size_t)(NUM_BOND_C - 1) * DD;
        agg_init_kernel<<<(unsigned)((ND4 + EL - 1) / EL), EL>>>(h, emb_self0, agg);
    }

    for (int l = 0; l < LL; l++) {
        const float* emb_l = edge_emb + (size_t)l * NUM_BOND_C * DD;

        scatter_edges_kernel<<<(EE + 7) / 8, 256>>>(h, edge_index, edge_attr, emb_l, agg);

        launch_gemm(agg, mlp_w1 + (size_t)l * DD * 2 * DD, mlp_b1 + (size_t)l * 2 * DD,
                    tmp, NN, DD, 2 * DD, 1, nullptr);

        zero_kernel<<<1, 512>>>(stat, 2 * DD);
        launch_gemm(tmp, mlp_w2 + (size_t)l * 2 * DD * DD, mlp_b2 + (size_t)l * DD,
                    h, NN, 2 * DD, DD, 0, stat);

        bn_finalize_kernel<<<1, 256>>>(stat, bn_gamma + (size_t)l * DD,
                                       bn_beta + (size_t)l * DD, ab);

        if (l < LL - 1) {
            const float* emb_self_next =
                edge_emb + (size_t)(l + 1) * NUM_BOND_C * DD + (size_t)(NUM_BOND_C - 1) * DD;
            bn_apply_agg_kernel<<<(unsigned)((ND4 + EL - 1) / EL), EL>>>(h, ab, emb_self_next,
                                                                         agg, 1);
        } else {
            bn_apply_agg_kernel<<<(unsigned)((ND4 + EL - 1) / EL), EL>>>(h, ab, nullptr,
                                                                         nullptr, 0);
        }
    }

    // feat = h @ feat_w + feat_b
    launch_gemm(h, feat_w, feat_b, tmp, NN, DD, FDIM, 0, nullptr);

    // global mean pool
    zero_kernel<<<(unsigned)(((size_t)GG * FDIM + EL - 1) / EL), EL>>>(ssum, (size_t)GG * FDIM);
    zero_kernel<<<(GG + EL - 1) / EL, EL>>>(cnt, GG);
    pool_count_kernel<<<(NN + EL - 1) / EL, EL>>>(batch, cnt);
    {
        size_t total = ((NN + 7) / 8) * (size_t)(FDIM / 4);
        pool_sum_kernel<<<(unsigned)((total + EL - 1) / EL), EL>>>(tmp, batch, ssum);
    }
    gfeat_kernel<<<(unsigned)(((size_t)GG * FDIM + EL - 1) / EL), EL>>>(ssum, cnt, gfeat);

    // head
    launch_gemm(gfeat, head_w1, head_b1, hid, GG, FDIM, FDIM / 2, 1, nullptr);
    head_out_kernel<<<(GG + 7) / 8, 256>>>(hid, head_w2, head_b2, out);
}

// round 3
// speedup vs baseline: 1.6554x; 1.2913x over previous
#include <cuda_runtime.h>
#include <math.h>
#include <stdint.h>

#define NN 100000
#define EE 300000
#define DD 256
#define FDIM 512
#define LL 5
#define GG 4000
#define NUM_BOND_C 2
#define BN_EPS 1e-5f

// ---------------- scratch (device globals: no allocation allowed) ----------------
__device__ float g_h[(size_t)NN * DD];
__device__ float g_agg[(size_t)NN * DD];
__device__ float g_tmp[(size_t)NN * FDIM];
__device__ float g_stat[2 * FDIM];
__device__ float g_ab[2 * DD];
__device__ float g_ssum[(size_t)GG * FDIM];
__device__ float g_cnt[GG];
__device__ float g_gfeat[(size_t)GG * FDIM];
__device__ float g_hid[(size_t)GG * (FDIM / 2)];

__device__ __forceinline__ float softplus_f(float x) {
    return fmaxf(x, 0.0f) + log1pf(expf(-fabsf(x)));
}

__device__ __forceinline__ void red_add_v4(float* p, float x, float y, float z, float w) {
    asm volatile("red.global.add.v4.f32 [%0], {%1,%2,%3,%4};"
                 :: "l"(p), "f"(x), "f"(y), "f"(z), "f"(w) : "memory");
}

__device__ __forceinline__ void red_add_f32(float* p, float v) {
    asm volatile("red.global.add.f32 [%0], %1;" :: "l"(p), "f"(v) : "memory");
}

// ---------------- tf32 helpers ----------------
__device__ __forceinline__ void split_tf32(float x, uint32_t& hi, uint32_t& lo) {
    uint32_t h = __float_as_uint(x) & 0xffffe000u;   // truncate to tf32 mantissa
    hi = h;
    lo = __float_as_uint(x - __uint_as_float(h));    // remainder (HW keeps its top bits)
}

__device__ __forceinline__ void mma8(float* c, const uint32_t* a, uint32_t b0, uint32_t b1) {
    asm volatile(
        "mma.sync.aligned.m16n8k8.row.col.f32.tf32.tf32.f32 "
        "{%0,%1,%2,%3},{%4,%5,%6,%7},{%8,%9},{%0,%1,%2,%3};"
        : "+f"(c[0]), "+f"(c[1]), "+f"(c[2]), "+f"(c[3])
        : "r"(a[0]), "r"(a[1]), "r"(a[2]), "r"(a[3]), "r"(b0), "r"(b1));
}

__device__ __forceinline__ void cpa16(void* dst, const void* src, int srcBytes) {
    uint32_t d = (uint32_t)__cvta_generic_to_shared(dst);
    asm volatile("cp.async.cg.shared.global [%0], [%1], 16, %2;"
                 :: "r"(d), "l"(src), "r"(srcBytes) : "memory");
}
__device__ __forceinline__ void cpa16f(void* dst, const void* src) {
    uint32_t d = (uint32_t)__cvta_generic_to_shared(dst);
    asm volatile("cp.async.cg.shared.global [%0], [%1], 16;"
                 :: "r"(d), "l"(src) : "memory");
}
__device__ __forceinline__ void cp_commit() {
    asm volatile("cp.async.commit_group;" ::: "memory");
}
__device__ __forceinline__ void cp_wait0() {
    asm volatile("cp.async.wait_group 0;" ::: "memory");
}

// ---------------- init: h = x_emb1[atomics] + pos @ x_emb2_w + b ----------------
__global__ void init_h_kernel(const int* __restrict__ atomics,
                              const float* __restrict__ pos,
                              const float* __restrict__ emb1,
                              const float* __restrict__ w2,
                              const float* __restrict__ b2,
                              float* __restrict__ h) {
    size_t idx = (size_t)blockIdx.x * blockDim.x + threadIdx.x;
    if (idx >= (size_t)NN * DD) return;
    int i = (int)(idx / DD);
    int d = (int)(idx & (DD - 1));
    float p0 = pos[i * 3 + 0], p1 = pos[i * 3 + 1], p2 = pos[i * 3 + 2];
    float v = emb1[(size_t)atomics[i] * DD + d];
    v += p0 * w2[d] + p1 * w2[DD + d] + p2 * w2[2 * DD + d] + b2[d];
    h[idx] = v;
}

// ---------------- agg = h + emb_self (float4) ----------------
__global__ void agg_init_kernel(const float* __restrict__ h,
                                const float* __restrict__ emb_self,
                                float* __restrict__ agg) {
    size_t idx = (size_t)blockIdx.x * blockDim.x + threadIdx.x;
    if (idx >= (size_t)NN * DD / 4) return;
    int d4 = (int)(idx & (DD / 4 - 1)) * 4;
    float4 hv = *((const float4*)h + idx);
    float4 ev = *(const float4*)(emb_self + d4);
    *((float4*)agg + idx) = make_float4(hv.x + ev.x, hv.y + ev.y, hv.z + ev.z, hv.w + ev.w);
}

// ---------------- scatter-add edges ----------------
__global__ void scatter_edges_kernel(const float* __restrict__ h,
                                     const int* __restrict__ edge_index,
                                     const int* __restrict__ edge_attr,
                                     const float* __restrict__ emb,
                                     float* __restrict__ agg) {
    int e = blockIdx.x * (blockDim.x >> 5) + (threadIdx.x >> 5);
    if (e >= EE) return;
    int lane = threadIdx.x & 31;
    int s = edge_index[e];
    int t = edge_index[EE + e];
    const float* hs = h + (size_t)s * DD;
    const float* eb = emb + (size_t)edge_attr[e] * DD;
    float* ag = agg + (size_t)t * DD;
#pragma unroll
    for (int half = 0; half < 2; half++) {
        int c = lane * 4 + half * 128;
        float4 hv = *(const float4*)(hs + c);
        float4 ev = *(const float4*)(eb + c);
        red_add_v4(ag + c, hv.x + ev.x, hv.y + ev.y, hv.z + ev.z, hv.w + ev.w);
    }
}

// ---------------- tf32x3 tensor-core GEMM ----------------
// C[M,Nc] = act(A[M,K] @ B[K,Nc] + bias); optional BN stats (sum/sumsq per col).
// 128x128x16 block tile, 256 threads = 8 warps (4x2), warp tile 32x64,
// mma.sync.m16n8k8 tf32, x3 compensation, cp.async double-buffered smem.
__global__ __launch_bounds__(256, 2)
void gemm_tf32(const float* __restrict__ A, const float* __restrict__ B,
               const float* __restrict__ bias, float* __restrict__ C,
               int M, int K, int Nc, int act, float* __restrict__ stat) {
    __shared__ float As[2][128][28];   // [buf][m][k] pad 28 -> conflict-free frag loads
    __shared__ float Bs[2][16][136];   // [buf][k][n] pad 136 -> conflict-free frag loads

    const int tid = threadIdx.x;
    const int lane = tid & 31;
    const int w = tid >> 5;
    const int g = lane >> 2;   // groupID  (0..7)
    const int t = lane & 3;    // threadID_in_group (0..3)
    const int warp_m = (w >> 1) * 32;
    const int warp_n = (w & 1) * 64;
    const int brow = blockIdx.y * 128;
    const int bcol = blockIdx.x * 128;

    // gmem->smem mapping
    const int a_row = tid >> 1;          // 0..127
    const int a_k = (tid & 1) * 8;       // 0 or 8
    const int b_k = tid >> 5;            // 0..7
    const int b_c = (tid & 31) * 4;      // 0..124

    const int a_grow = brow + a_row;
    const int a_bytes = (a_grow < M) ? 16 : 0;
    const float* Ag = A + (size_t)((a_grow < M) ? a_grow : 0) * K + a_k;
    const float* Bg = B + (size_t)b_k * Nc + bcol + b_c;

    float acc[2][8][4];
#pragma unroll
    for (int mt = 0; mt < 2; mt++)
#pragma unroll
        for (int nt = 0; nt < 8; nt++)
#pragma unroll
            for (int q = 0; q < 4; q++) acc[mt][nt][q] = 0.0f;

    const int T = K >> 4;

    // prologue: stage 0
    cpa16(&As[0][a_row][a_k], Ag, a_bytes);
    cpa16(&As[0][a_row][a_k + 4], Ag + 4, a_bytes);
    cpa16f(&Bs[0][b_k][b_c], Bg);
    cpa16f(&Bs[0][b_k + 8][b_c], Bg + (size_t)8 * Nc);
    cp_commit();

    for (int s = 0; s < T; s++) {
        const int buf = s & 1;
        cp_wait0();
        __syncthreads();
        if (s + 1 < T) {
            const int nb = buf ^ 1;
            const int ko = (s + 1) << 4;
            cpa16(&As[nb][a_row][a_k], Ag + ko, a_bytes);
            cpa16(&As[nb][a_row][a_k + 4], Ag + ko + 4, a_bytes);
            cpa16f(&Bs[nb][b_k][b_c], Bg + (size_t)ko * Nc);
            cpa16f(&Bs[nb][b_k + 8][b_c], Bg + (size_t)(ko + 8) * Nc);
            cp_commit();
        } else {
            cp_commit();  // keep wait_group balanced
        }

#pragma unroll
        for (int kk = 0; kk < 16; kk += 8) {
            uint32_t ah[2][4], al[2][4];
#pragma unroll
            for (int mt = 0; mt < 2; mt++) {
                const int mr = warp_m + mt * 16 + g;
                float r0 = As[buf][mr][kk + t];
                float r1 = As[buf][mr + 8][kk + t];
                float r2 = As[buf][mr][kk + t + 4];
                float r3 = As[buf][mr + 8][kk + t + 4];
                split_tf32(r0, ah[mt][0], al[mt][0]);
                split_tf32(r1, ah[mt][1], al[mt][1]);
                split_tf32(r2, ah[mt][2], al[mt][2]);
                split_tf32(r3, ah[mt][3], al[mt][3]);
            }
#pragma unroll
            for (int nt = 0; nt < 8; nt++) {
                const int nc_ = warp_n + nt * 8 + g;
                float q0 = Bs[buf][kk + t][nc_];
                float q1 = Bs[buf][kk + t + 4][nc_];
                uint32_t bh0, bl0, bh1, bl1;
                split_tf32(q0, bh0, bl0);
                split_tf32(q1, bh1, bl1);
#pragma unroll
                for (int mt = 0; mt < 2; mt++) {
                    mma8(acc[mt][nt], ah[mt], bh0, bh1);
                    mma8(acc[mt][nt], ah[mt], bl0, bl1);
                    mma8(acc[mt][nt], al[mt], bh0, bh1);
                }
            }
        }
        // next iteration's wait+sync protects buffer reuse
    }

    // ---------------- epilogue ----------------
    const bool do_stats = (stat != nullptr);
    float csum[16], csq[16];
    if (do_stats) {
#pragma unroll
        for (int i = 0; i < 16; i++) { csum[i] = 0.f; csq[i] = 0.f; }
    }

#pragma unroll
    for (int mt = 0; mt < 2; mt++) {
        const int r0 = brow + warp_m + mt * 16 + g;
#pragma unroll
        for (int nt = 0; nt < 8; nt++) {
            const int col = bcol + warp_n + nt * 8 + t * 2;
            const float b0v = bias[col];
            const float b1v = bias[col + 1];
            float v0 = acc[mt][nt][0] + b0v;
            float v1 = acc[mt][nt][1] + b1v;
            float v2 = acc[mt][nt][2] + b0v;
            float v3 = acc[mt][nt][3] + b1v;
            if (act) {
                v0 = softplus_f(v0); v1 = softplus_f(v1);
                v2 = softplus_f(v2); v3 = softplus_f(v3);
            }
            if (r0 < M) {
                *(float2*)&C[(size_t)r0 * Nc + col] = make_float2(v0, v1);
                if (do_stats) {
                    csum[nt * 2] += v0; csq[nt * 2] += v0 * v0;
                    csum[nt * 2 + 1] += v1; csq[nt * 2 + 1] += v1 * v1;
                }
            }
            if (r0 + 8 < M) {
                *(float2*)&C[(size_t)(r0 + 8) * Nc + col] = make_float2(v2, v3);
                if (do_stats) {
                    csum[nt * 2] += v2; csq[nt * 2] += v2 * v2;
                    csum[nt * 2 + 1] += v3; csq[nt * 2 + 1] += v3 * v3;
                }
            }
        }
    }

    if (do_stats) {
#pragma unroll
        for (int i = 0; i < 16; i++) {
            float sv = csum[i], qv = csq[i];
            sv += __shfl_xor_sync(0xffffffffu, sv, 4);
            sv += __shfl_xor_sync(0xffffffffu, sv, 8);
            sv += __shfl_xor_sync(0xffffffffu, sv, 16);
            qv += __shfl_xor_sync(0xffffffffu, qv, 4);
            qv += __shfl_xor_sync(0xffffffffu, qv, 8);
            qv += __shfl_xor_sync(0xffffffffu, qv, 16);
            if (g == 0) {
                const int col = bcol + warp_n + (i >> 1) * 8 + t * 2 + (i & 1);
                red_add_f32(&stat[col], sv);
                red_add_f32(&stat[Nc + col], qv);
            }
        }
    }
}

// ---------------- BN ----------------
__global__ void zero_kernel(float* __restrict__ p, size_t n) {
    size_t idx = (size_t)blockIdx.x * blockDim.x + threadIdx.x;
    if (idx < n) p[idx] = 0.0f;
}

__global__ void bn_finalize_kernel(const float* __restrict__ stat,
                                   const float* __restrict__ gamma,
                                   const float* __restrict__ beta,
                                   float* __restrict__ ab) {
    int d = threadIdx.x;
    float mean = stat[d] * (1.0f / NN);
    float var = stat[DD + d] * (1.0f / NN) - mean * mean;
    float inv = rsqrtf(var + BN_EPS);
    float a = gamma[d] * inv;
    ab[d] = a;
    ab[DD + d] = beta[d] - mean * a;
}

__global__ void bn_apply_agg_kernel(float* __restrict__ h, const float* __restrict__ ab,
                                    const float* __restrict__ emb_next,
                                    float* __restrict__ agg, int act) {
    size_t idx = (size_t)blockIdx.x * blockDim.x + threadIdx.x;
    if (idx >= (size_t)NN * DD / 4) return;
    int d4 = (int)(idx & (DD / 4 - 1)) * 4;
    float4 v = *((float4*)h + idx);
    float4 a = *(const float4*)(ab + d4);
    float4 b = *(const float4*)(ab + DD + d4);
    v.x = v.x * a.x + b.x;
    v.y = v.y * a.y + b.y;
    v.z = v.z * a.z + b.z;
    v.w = v.w * a.w + b.w;
    if (act) {
        v.x = softplus_f(v.x);
        v.y = softplus_f(v.y);
        v.z = softplus_f(v.z);
        v.w = softplus_f(v.w);
    }
    *((float4*)h + idx) = v;
    if (agg) {
        float4 e = *(const float4*)(emb_next + d4);
        *((float4*)agg + idx) = make_float4(v.x + e.x, v.y + e.y, v.z + e.z, v.w + e.w);
    }
}

// ---------------- pooling ----------------
__global__ void pool_count_kernel(const int* __restrict__ batch, float* __restrict__ cnt) {
    int i = blockIdx.x * blockDim.x + threadIdx.x;
    if (i >= NN) return;
    atomicAdd(&cnt[batch[i]], 1.0f);
}

__global__ void pool_sum_kernel(const float* __restrict__ feat,
                                const int* __restrict__ batch,
                                float* __restrict__ ssum) {
    size_t idx = (size_t)blockIdx.x * blockDim.x + threadIdx.x;
    const int CH = FDIM / 4;
    const size_t nchunks = (NN + 7) / 8;
    if (idx >= nchunks * CH) return;
    int f4 = (int)(idx & (CH - 1)) * 4;
    int i0 = (int)(idx / CH) * 8;
    int cur = batch[i0];
    float4 acc = make_float4(0.f, 0.f, 0.f, 0.f);
#pragma unroll
    for (int r = 0; r < 8; r++) {
        int i = i0 + r;
        if (i >= NN) break;
        int b = batch[i];
        if (b != cur) {
            red_add_v4(&ssum[(size_t)cur * FDIM + f4], acc.x, acc.y, acc.z, acc.w);
            acc = make_float4(0.f, 0.f, 0.f, 0.f);
            cur = b;
        }
        float4 v = *(const float4*)(feat + (size_t)i * FDIM + f4);
        acc.x += v.x; acc.y += v.y; acc.z += v.z; acc.w += v.w;
    }
    red_add_v4(&ssum[(size_t)cur * FDIM + f4], acc.x, acc.y, acc.z, acc.w);
}

__global__ void gfeat_kernel(const float* __restrict__ ssum, const float* __restrict__ cnt,
                             float* __restrict__ gfeat) {
    size_t idx = (size_t)blockIdx.x * blockDim.x + threadIdx.x;
    if (idx >= (size_t)GG * FDIM) return;
    int g = (int)(idx / FDIM);
    gfeat[idx] = ssum[idx] / fmaxf(cnt[g], 1.0f);
}

// ---------------- final head ----------------
__global__ void head_out_kernel(const float* __restrict__ hid, const float* __restrict__ w2,
                                const float* __restrict__ b2, float* __restrict__ out) {
    int g = blockIdx.x * (blockDim.x >> 5) + (threadIdx.x >> 5);
    if (g >= GG) return;
    int lane = threadIdx.x & 31;
    const float* hr = hid + (size_t)g * (FDIM / 2);
    float s = 0.f;
#pragma unroll
    for (int k = lane; k < FDIM / 2; k += 32) s += hr[k] * w2[k];
#pragma unroll
    for (int o = 16; o; o >>= 1) s += __shfl_down_sync(0xffffffffu, s, o);
    if (lane == 0) out[g] = s + b2[0];
}

// ---------------- host launch ----------------
static inline void launch_gemm(const float* A, const float* B, const float* bias, float* C,
                               int M, int K, int Nc, int act, float* stat) {
    dim3 grid((Nc + 127) / 128, (M + 127) / 128);
    gemm_tf32<<<grid, 256>>>(A, B, bias, C, M, K, Nc, act, stat);
}

extern "C" void kernel_launch(void* const* d_in, const int* in_sizes, int n_in,
                              void* d_out, int out_size) {
    const int* atomics = (const int*)d_in[0];
    const float* pos = (const float*)d_in[1];
    const int* edge_index = (const int*)d_in[2];
    const int* edge_attr = (const int*)d_in[3];
    const int* batch = (const int*)d_in[4];
    const float* x_emb1 = (const float*)d_in[5];
    const float* x_emb2_w = (const float*)d_in[6];
    const float* x_emb2_b = (const float*)d_in[7];
    const float* edge_emb = (const float*)d_in[8];
    const float* mlp_w1 = (const float*)d_in[9];
    const float* mlp_b1 = (const float*)d_in[10];
    const float* mlp_w2 = (const float*)d_in[11];
    const float* mlp_b2 = (const float*)d_in[12];
    const float* bn_gamma = (const float*)d_in[13];
    const float* bn_beta = (const float*)d_in[14];
    const float* feat_w = (const float*)d_in[15];
    const float* feat_b = (const float*)d_in[16];
    const float* head_w1 = (const float*)d_in[17];
    const float* head_b1 = (const float*)d_in[18];
    const float* head_w2 = (const float*)d_in[19];
    const float* head_b2 = (const float*)d_in[20];
    float* out = (float*)d_out;

    float *h, *agg, *tmp, *stat, *ab, *ssum, *cnt, *gfeat, *hid;
    cudaGetSymbolAddress((void**)&h, g_h);
    cudaGetSymbolAddress((void**)&agg, g_agg);
    cudaGetSymbolAddress((void**)&tmp, g_tmp);
    cudaGetSymbolAddress((void**)&stat, g_stat);
    cudaGetSymbolAddress((void**)&ab, g_ab);
    cudaGetSymbolAddress((void**)&ssum, g_ssum);
    cudaGetSymbolAddress((void**)&cnt, g_cnt);
    cudaGetSymbolAddress((void**)&gfeat, g_gfeat);
    cudaGetSymbolAddress((void**)&hid, g_hid);

    const size_t ND = (size_t)NN * DD;
    const size_t ND4 = ND / 4;
    const int EL = 256;

    init_h_kernel<<<(unsigned)((ND + EL - 1) / EL), EL>>>(atomics, pos, x_emb1, x_emb2_w,
                                                          x_emb2_b, h);
    {
        const float* emb_self0 =
            edge_emb + (size_t)0 * NUM_BOND_C * DD + (size_t)(NUM_BOND_C - 1) * DD;
        agg_init_kernel<<<(unsigned)((ND4 + EL - 1) / EL), EL>>>(h, emb_self0, agg);
    }

    for (int l = 0; l < LL; l++) {
        const float* emb_l = edge_emb + (size_t)l * NUM_BOND_C * DD;

        scatter_edges_kernel<<<(EE + 7) / 8, 256>>>(h, edge_index, edge_attr, emb_l, agg);

        launch_gemm(agg, mlp_w1 + (size_t)l * DD * 2 * DD, mlp_b1 + (size_t)l * 2 * DD,
                    tmp, NN, DD, 2 * DD, 1, nullptr);

        zero_kernel<<<1, 512>>>(stat, 2 * DD);
        launch_gemm(tmp, mlp_w2 + (size_t)l * 2 * DD * DD, mlp_b2 + (size_t)l * DD,
                    h, NN, 2 * DD, DD, 0, stat);

        bn_finalize_kernel<<<1, 256>>>(stat, bn_gamma + (size_t)l * DD,
                                       bn_beta + (size_t)l * DD, ab);

        if (l < LL - 1) {
            const float* emb_self_next =
                edge_emb + (size_t)(l + 1) * NUM_BOND_C * DD + (size_t)(NUM_BOND_C - 1) * DD;
            bn_apply_agg_kernel<<<(unsigned)((ND4 + EL - 1) / EL), EL>>>(h, ab, emb_self_next,
                                                                         agg, 1);
        } else {
            bn_apply_agg_kernel<<<(unsigned)((ND4 + EL - 1) / EL), EL>>>(h, ab, nullptr,
                                                                         nullptr, 0);
        }
    }

    // feat = h @ feat_w + feat_b
    launch_gemm(h, feat_w, feat_b, tmp, NN, DD, FDIM, 0, nullptr);

    // global mean pool
    zero_kernel<<<(unsigned)(((size_t)GG * FDIM + EL - 1) / EL), EL>>>(ssum, (size_t)GG * FDIM);
    zero_kernel<<<(GG + EL - 1) / EL, EL>>>(cnt, GG);
    pool_count_kernel<<<(NN + EL - 1) / EL, EL>>>(batch, cnt);
    {
        size_t total = ((NN + 7) / 8) * (size_t)(FDIM / 4);
        pool_sum_kernel<<<(unsigned)((total + EL - 1) / EL), EL>>>(tmp, batch, ssum);
    }
    gfeat_kernel<<<(unsigned)(((size_t)GG * FDIM + EL - 1) / EL), EL>>>(ssum, cnt, gfeat);

    // head
    launch_gemm(gfeat, head_w1, head_b1, hid, GG, FDIM, FDIM / 2, 1, nullptr);
    head_out_kernel<<<(GG + 7) / 8, 256>>>(hid, head_w2, head_b2, out);
}